// round 2
// baseline (speedup 1.0000x reference)
#include <cuda_runtime.h>
#include <math.h>

// ---------------- scratch (allocation-free: __device__ globals) ----------------
__device__ float g_bufA[660000];
__device__ float g_bufB[660000];
__device__ float g_h[100 * 512];
__device__ float g_q[4 * 100 * 128];
__device__ float g_k[4 * 100 * 128];
__device__ float g_v[4 * 100 * 256];
__device__ float g_ocat[100 * 1024];
__device__ float g_ffn[100 * 2048];

// ---------------- conv layers ----------------
// Each patch: input CIN x HIN x HIN in smem; thread handles (co, out-row) pairs,
// accumulating a full output row in registers (weight reuse across WOUT pixels).
template <int CIN, int HIN, int COUT, int KS, int COG, bool RELU, bool FIRST>
__global__ __launch_bounds__(128) void conv_kernel(
    const float* __restrict__ in, const float* __restrict__ W,
    const float* __restrict__ bias, float* __restrict__ out)
{
    constexpr int HOUT = HIN - KS + 1;
    constexpr int WOUT = HOUT;
    constexpr int INSZ = CIN * HIN * HIN;
    constexpr int HW = HOUT * WOUT;
    __shared__ float sin_[INSZ];

    const int p = blockIdx.x;
    const int co0 = blockIdx.y * COG;

    if (FIRST) {
        // gather patch p from x[3,200,200]; p = i_blk*10 + j_blk
        const int ib = p / 10, jb = p % 10;
        for (int idx = threadIdx.x; idx < INSZ; idx += blockDim.x) {
            const int c = idx / (HIN * HIN);
            const int rem = idx % (HIN * HIN);
            const int r = rem / HIN, cc = rem % HIN;
            sin_[idx] = in[c * 40000 + (20 * jb + r) * 200 + (20 * ib + cc)];
        }
    } else {
        const float* src = in + p * INSZ;
        for (int idx = threadIdx.x; idx < INSZ; idx += blockDim.x)
            sin_[idx] = src[idx];
    }
    __syncthreads();

    for (int pair = threadIdx.x; pair < COG * HOUT; pair += blockDim.x) {
        const int co = co0 + pair / HOUT;
        const int py = pair % HOUT;
        float acc[WOUT];
        const float bv = bias[co];
#pragma unroll
        for (int px = 0; px < WOUT; px++) acc[px] = bv;
        const float* wbase = W + co * CIN * KS * KS;
        for (int ci = 0; ci < CIN; ci++) {
#pragma unroll
            for (int ky = 0; ky < KS; ky++) {
                const float* irow = sin_ + ci * HIN * HIN + (py + ky) * HIN;
                float w[KS];
#pragma unroll
                for (int kx = 0; kx < KS; kx++)
                    w[kx] = wbase[ci * KS * KS + ky * KS + kx];
#pragma unroll
                for (int px = 0; px < WOUT; px++) {
#pragma unroll
                    for (int kx = 0; kx < KS; kx++)
                        acc[px] += w[kx] * irow[px + kx];
                }
            }
        }
        float* orow = out + p * COUT * HW + co * HW + py * WOUT;
#pragma unroll
        for (int px = 0; px < WOUT; px++) {
            float v = acc[px];
            if (RELU) v = fmaxf(v, 0.0f);
            orow[px] = v;
        }
    }
}

// ---------------- location embedding add ----------------
__global__ __launch_bounds__(256) void locadd_kernel(const float* __restrict__ conv_out,
                                                     float* __restrict__ h)
{
    int i = blockIdx.x * blockDim.x + threadIdx.x;
    if (i >= 100 * 512) return;
    const int n = i >> 9;
    const int d = i & 511;
    const float pos = 20.0f * (float)(n / 10);
    const int k = d & 255;
    // 1 / 10000^(2k/256) = 2^(-k * 2*log2(10000)/256)
    const float ang = pos * exp2f(-0.10381025296523009f * (float)k);
    const float e = (d < 256) ? sinf(ang) : cosf(ang);
    h[i] = conv_out[i] + e;
}

// ---------------- fp32 tiled GEMM core (64x64 tile, 16 k-step, 256 thr) ------
// C[M,N] = A[M,K](row) * B[K,N](row)  [+bias[n]] [relu] [+resid[m,n]]
__device__ __forceinline__ void gemm_tile(
    const float* __restrict__ A, const float* __restrict__ B, float* __restrict__ C,
    int M, int N, int K,
    const float* __restrict__ bias, const float* __restrict__ resid, bool relu,
    int bm, int bn)
{
    __shared__ float As[16][68];  // [k][m], padded
    __shared__ float Bs[16][64];  // [k][n]
    const int tid = threadIdx.x;
    const int tx = tid & 15, ty = tid >> 4;
    float acc[4][4] = {};
    const int m0 = bm * 64, n0 = bn * 64;

    for (int k0 = 0; k0 < K; k0 += 16) {
#pragma unroll
        for (int i = 0; i < 4; i++) {
            const int idx = tid + i * 256;
            const int m = idx >> 4, kk = idx & 15;
            As[kk][m] = (m0 + m < M) ? A[(m0 + m) * K + (k0 + kk)] : 0.0f;
        }
#pragma unroll
        for (int i = 0; i < 4; i++) {
            const int idx = tid + i * 256;
            const int kk = idx >> 6, n = idx & 63;
            Bs[kk][n] = B[(k0 + kk) * N + (n0 + n)];
        }
        __syncthreads();
#pragma unroll
        for (int kk = 0; kk < 16; kk++) {
            float a[4], b[4];
#pragma unroll
            for (int i = 0; i < 4; i++) a[i] = As[kk][ty + 16 * i];
#pragma unroll
            for (int j = 0; j < 4; j++) b[j] = Bs[kk][tx + 16 * j];
#pragma unroll
            for (int i = 0; i < 4; i++)
#pragma unroll
                for (int j = 0; j < 4; j++) acc[i][j] += a[i] * b[j];
        }
        __syncthreads();
    }
#pragma unroll
    for (int i = 0; i < 4; i++) {
        const int m = m0 + ty + 16 * i;
        if (m >= M) continue;
#pragma unroll
        for (int j = 0; j < 4; j++) {
            const int n = n0 + tx + 16 * j;
            float v = acc[i][j];
            if (bias) v += bias[n];
            if (relu) v = fmaxf(v, 0.0f);
            if (resid) v += resid[m * N + n];
            C[m * N + n] = v;
        }
    }
}

__global__ __launch_bounds__(256) void sgemm_kernel(
    const float* __restrict__ A, const float* __restrict__ B, float* __restrict__ C,
    int M, int N, int K,
    const float* __restrict__ bias, const float* __restrict__ resid, int relu)
{
    gemm_tile(A, B, C, M, N, K, bias, resid, relu != 0, blockIdx.x, blockIdx.y);
}

// QKV: grid (2, 4, 12). z<4: Q head z; z<8: K head z-4; else V head z-8.
__global__ __launch_bounds__(256) void qkv_kernel(
    const float* __restrict__ h, const float* __restrict__ Wq,
    const float* __restrict__ Wk, const float* __restrict__ Wv)
{
    const int z = blockIdx.z;
    const float* B;
    float* C;
    int N;
    if (z < 4)      { N = 128; B = Wq + z * 512 * 128;       C = g_q + z * 100 * 128; }
    else if (z < 8) { N = 128; B = Wk + (z - 4) * 512 * 128; C = g_k + (z - 4) * 100 * 128; }
    else            { N = 256; B = Wv + (z - 8) * 512 * 256; C = g_v + (z - 8) * 100 * 256; }
    if ((int)blockIdx.y * 64 >= N) return;
    gemm_tile(h, B, C, 100, N, 512, nullptr, nullptr, false, blockIdx.x, blockIdx.y);
}

// ---------------- attention: per-head K,V resident in smem ----------------
// grid (4 heads, 10 row-groups of 10 rows), 256 threads.
// scale = 1/sqrt(N_LOC) = 0.1 (faithful quirk).
#define ATTN_SMEM ((100 * 129 + 100 * 256) * 4)
__global__ __launch_bounds__(256) void attn_kernel()
{
    extern __shared__ float sm[];
    float* ks = sm;               // [100][129] padded
    float* vs = sm + 100 * 129;   // [100][256]
    __shared__ float qrow[128];
    __shared__ float srow[100];
    __shared__ float red[2];

    const int h = blockIdx.x;
    const int rg = blockIdx.y;
    const int tid = threadIdx.x;

    for (int idx = tid; idx < 100 * 128; idx += 256) {
        const int m = idx >> 7, d = idx & 127;
        ks[m * 129 + d] = g_k[h * 12800 + idx];
    }
    for (int idx = tid; idx < 100 * 256; idx += 256)
        vs[idx] = g_v[h * 25600 + idx];
    __syncthreads();

    for (int r = 0; r < 10; r++) {
        const int n = rg * 10 + r;
        if (tid < 128) qrow[tid] = g_q[(h * 100 + n) * 128 + tid];
        __syncthreads();
        if (tid < 100) {
            float acc = 0.0f;
#pragma unroll 4
            for (int d = 0; d < 128; d++) acc += qrow[d] * ks[tid * 129 + d];
            srow[tid] = acc * 0.1f;
        }
        __syncthreads();
        if (tid < 32) {
            float mx = -1e30f;
            for (int i = tid; i < 100; i += 32) mx = fmaxf(mx, srow[i]);
#pragma unroll
            for (int o = 16; o; o >>= 1) mx = fmaxf(mx, __shfl_xor_sync(0xffffffffu, mx, o));
            if (tid == 0) red[0] = mx;
        }
        __syncthreads();
        if (tid < 100) srow[tid] = __expf(srow[tid] - red[0]);
        __syncthreads();
        if (tid < 32) {
            float sum = 0.0f;
            for (int i = tid; i < 100; i += 32) sum += srow[i];
#pragma unroll
            for (int o = 16; o; o >>= 1) sum += __shfl_xor_sync(0xffffffffu, sum, o);
            if (tid == 0) red[1] = 1.0f / sum;
        }
        __syncthreads();
        {
            const float inv = red[1];
            const int dv = tid;  // 0..255
            float acc = 0.0f;
            for (int m = 0; m < 100; m++) acc += srow[m] * vs[m * 256 + dv];
            g_ocat[n * 1024 + h * 256 + dv] = acc * inv;
        }
        __syncthreads();
    }
}

// ---------------- launch ----------------
extern "C" void kernel_launch(void* const* d_in, const int* in_sizes, int n_in,
                              void* d_out, int out_size)
{
    (void)in_sizes; (void)n_in; (void)out_size;
    const float* x = (const float*)d_in[0];
    const float* cw[10];
    const float* cb[10];
    for (int i = 0; i < 10; i++) {
        cw[i] = (const float*)d_in[1 + 2 * i];
        cb[i] = (const float*)d_in[2 + 2 * i];
    }
    const float* Wq = (const float*)d_in[21];
    const float* Wk = (const float*)d_in[22];
    const float* Wv = (const float*)d_in[23];
    const float* Wo = (const float*)d_in[24];
    const float* W1 = (const float*)d_in[25];
    const float* b1 = (const float*)d_in[26];
    const float* W2 = (const float*)d_in[27];
    const float* b2 = (const float*)d_in[28];

    float *bufA, *bufB, *h, *ocat, *ffn;
    cudaGetSymbolAddress((void**)&bufA, g_bufA);
    cudaGetSymbolAddress((void**)&bufB, g_bufB);
    cudaGetSymbolAddress((void**)&h, g_h);
    cudaGetSymbolAddress((void**)&ocat, g_ocat);
    cudaGetSymbolAddress((void**)&ffn, g_ffn);

    cudaFuncSetAttribute(attn_kernel, cudaFuncAttributeMaxDynamicSharedMemorySize, ATTN_SMEM);

    // Conv stack (RELU_AFTER = F T F T T T T T T F)
    conv_kernel<3, 20, 8, 3, 8, false, true><<<dim3(100, 1), 128>>>(x, cw[0], cb[0], bufA);
    conv_kernel<8, 18, 16, 3, 8, true, false><<<dim3(100, 2), 128>>>(bufA, cw[1], cb[1], bufB);
    conv_kernel<16, 16, 32, 3, 8, false, false><<<dim3(100, 4), 128>>>(bufB, cw[2], cb[2], bufA);
    conv_kernel<32, 14, 32, 3, 8, true, false><<<dim3(100, 4), 128>>>(bufA, cw[3], cb[3], bufB);
    conv_kernel<32, 12, 64, 3, 16, true, false><<<dim3(100, 4), 128>>>(bufB, cw[4], cb[4], bufA);
    conv_kernel<64, 10, 64, 3, 16, true, false><<<dim3(100, 4), 128>>>(bufA, cw[5], cb[5], bufB);
    conv_kernel<64, 8, 128, 3, 32, true, false><<<dim3(100, 4), 128>>>(bufB, cw[6], cb[6], bufA);
    conv_kernel<128, 6, 128, 3, 32, true, false><<<dim3(100, 4), 128>>>(bufA, cw[7], cb[7], bufB);
    conv_kernel<128, 4, 256, 3, 64, true, false><<<dim3(100, 4), 128>>>(bufB, cw[8], cb[8], bufA);
    conv_kernel<256, 2, 512, 2, 128, false, false><<<dim3(100, 4), 128>>>(bufA, cw[9], cb[9], bufB);

    locadd_kernel<<<200, 256>>>(bufB, h);

    for (int n = 0; n < 12; n++) {
        qkv_kernel<<<dim3(2, 4, 12), 256>>>(h, Wq + n * 262144, Wk + n * 262144,
                                            Wv + n * 524288);
        attn_kernel<<<dim3(4, 10), 256, ATTN_SMEM>>>();
        // h = h + ocat @ Wo
        sgemm_kernel<<<dim3(2, 8), 256>>>(ocat, Wo + n * 524288, h,
                                          100, 512, 1024, nullptr, h, 0);
        // ffn = relu(h @ W1 + b1)
        sgemm_kernel<<<dim3(2, 32), 256>>>(h, W1 + n * 1048576, ffn,
                                           100, 2048, 512, b1 + n * 2048, nullptr, 1);
        // h = h + ffn @ W2 + b2   (last layer writes d_out directly)
        float* outp = (n == 11) ? (float*)d_out : h;
        sgemm_kernel<<<dim3(2, 8), 256>>>(ffn, W2 + n * 1048576, outp,
                                          100, 512, 2048, b2 + n * 512, h, 0);
    }
}

// round 4
// speedup vs baseline: 2.8470x; 2.8470x over previous
#include <cuda_runtime.h>
#include <math.h>

// ---------------- scratch (allocation-free: __device__ globals) ----------------
__device__ float g_bufA[660000];
__device__ float g_bufB[660000];
__device__ float g_h[100 * 512];
__device__ float g_q[4 * 100 * 128];
__device__ float g_k[4 * 100 * 128];
__device__ float g_v[4 * 100 * 256];
__device__ float g_ocat[100 * 1024];
__device__ float g_ffn[100 * 2048];
__device__ float g_part[409600];   // split-K partials (max 8x100x512 / 2x100x2048)

// ---------------- conv layers 1-9 (unchanged row-strip kernel) ----------------
template <int CIN, int HIN, int COUT, int KS, int COG, bool RELU, bool FIRST>
__global__ __launch_bounds__(128) void conv_kernel(
    const float* __restrict__ in, const float* __restrict__ W,
    const float* __restrict__ bias, float* __restrict__ out)
{
    constexpr int HOUT = HIN - KS + 1;
    constexpr int WOUT = HOUT;
    constexpr int INSZ = CIN * HIN * HIN;
    constexpr int HW = HOUT * WOUT;
    __shared__ float sin_[INSZ];

    const int p = blockIdx.x;
    const int co0 = blockIdx.y * COG;

    if (FIRST) {
        const int ib = p / 10, jb = p % 10;
        for (int idx = threadIdx.x; idx < INSZ; idx += blockDim.x) {
            const int c = idx / (HIN * HIN);
            const int rem = idx % (HIN * HIN);
            const int r = rem / HIN, cc = rem % HIN;
            sin_[idx] = in[c * 40000 + (20 * jb + r) * 200 + (20 * ib + cc)];
        }
    } else {
        const float* src = in + p * INSZ;
        for (int idx = threadIdx.x; idx < INSZ; idx += blockDim.x)
            sin_[idx] = src[idx];
    }
    __syncthreads();

    for (int pair = threadIdx.x; pair < COG * HOUT; pair += blockDim.x) {
        const int co = co0 + pair / HOUT;
        const int py = pair % HOUT;
        float acc[WOUT];
        const float bv = bias[co];
#pragma unroll
        for (int px = 0; px < WOUT; px++) acc[px] = bv;
        const float* wbase = W + co * CIN * KS * KS;
        for (int ci = 0; ci < CIN; ci++) {
#pragma unroll
            for (int ky = 0; ky < KS; ky++) {
                const float* irow = sin_ + ci * HIN * HIN + (py + ky) * HIN;
                float w[KS];
#pragma unroll
                for (int kx = 0; kx < KS; kx++)
                    w[kx] = wbase[ci * KS * KS + ky * KS + kx];
#pragma unroll
                for (int px = 0; px < WOUT; px++) {
#pragma unroll
                    for (int kx = 0; kx < KS; kx++)
                        acc[px] += w[kx] * irow[px + kx];
                }
            }
        }
        float* orow = out + p * COUT * HW + co * HW + py * WOUT;
#pragma unroll
        for (int px = 0; px < WOUT; px++) {
            float v = acc[px];
            if (RELU) v = fmaxf(v, 0.0f);
            orow[px] = v;
        }
    }
}

// ---------------- location embedding add ----------------
__global__ __launch_bounds__(256) void locadd_kernel(const float* __restrict__ conv_out,
                                                     float* __restrict__ h)
{
    int i = blockIdx.x * blockDim.x + threadIdx.x;
    if (i >= 100 * 512) return;
    const int n = i >> 9;
    const int d = i & 511;
    const float pos = 20.0f * (float)(n / 10);
    const int k = d & 255;
    const float ang = pos * exp2f(-0.10381025296523009f * (float)k);
    const float e = (d < 256) ? sinf(ang) : cosf(ang);
    h[i] = conv_out[i] + e;
}

// ================= fp32 GEMM v2: 64x64x16 tile, double-buffered, float4 ======
// A: row-major, row stride K (pointer pre-offset to m0*K + kstart)
// B: normal -> row-major [K,N], pre-offset kstart*N + n0
//    BT     -> row-major [N,K], pre-offset n0*K + kstart
template<bool BT>
__device__ __forceinline__ void gemm_mainloop(
    const float* __restrict__ A, const float* __restrict__ B,
    int K, int N, int nk, int mvalid, float acc[4][4])
{
    __shared__ float As[2][16][68];
    __shared__ float Bs[2][16][68];
    const int tid = threadIdx.x;
    const int tx = tid & 15, ty = tid >> 4;
    const int am = tid >> 2, ac = tid & 3;     // A (and BT) loader coords
    const int bk = tid >> 4, bn4 = (tid & 15) * 4;  // B normal loader coords
    const float4 z4 = make_float4(0.f, 0.f, 0.f, 0.f);

    float4 ra, rb;
    ra = (am < mvalid) ? *(const float4*)(A + am * K + ac * 4) : z4;
    if (BT) rb = *(const float4*)(B + am * K + ac * 4);
    else    rb = *(const float4*)(B + bk * N + bn4);

    As[0][ac * 4 + 0][am] = ra.x; As[0][ac * 4 + 1][am] = ra.y;
    As[0][ac * 4 + 2][am] = ra.z; As[0][ac * 4 + 3][am] = ra.w;
    if (BT) {
        Bs[0][ac * 4 + 0][am] = rb.x; Bs[0][ac * 4 + 1][am] = rb.y;
        Bs[0][ac * 4 + 2][am] = rb.z; Bs[0][ac * 4 + 3][am] = rb.w;
    } else {
        *(float4*)&Bs[0][bk][bn4] = rb;
    }
    __syncthreads();

    for (int kt = 0; kt < nk; kt++) {
        const int cur = kt & 1, nxt = cur ^ 1;
        if (kt + 1 < nk) {
            const float* An = A + (kt + 1) * 16;
            ra = (am < mvalid) ? *(const float4*)(An + am * K + ac * 4) : z4;
            if (BT) rb = *(const float4*)(B + (kt + 1) * 16 + am * K + ac * 4);
            else    rb = *(const float4*)(B + (size_t)(kt + 1) * 16 * N + bk * N + bn4);
        }
#pragma unroll
        for (int kk = 0; kk < 16; kk++) {
            const float4 a = *(const float4*)&As[cur][kk][ty * 4];
            const float4 b = *(const float4*)&Bs[cur][kk][tx * 4];
            acc[0][0] += a.x * b.x; acc[0][1] += a.x * b.y; acc[0][2] += a.x * b.z; acc[0][3] += a.x * b.w;
            acc[1][0] += a.y * b.x; acc[1][1] += a.y * b.y; acc[1][2] += a.y * b.z; acc[1][3] += a.y * b.w;
            acc[2][0] += a.z * b.x; acc[2][1] += a.z * b.y; acc[2][2] += a.z * b.z; acc[2][3] += a.z * b.w;
            acc[3][0] += a.w * b.x; acc[3][1] += a.w * b.y; acc[3][2] += a.w * b.z; acc[3][3] += a.w * b.w;
        }
        if (kt + 1 < nk) {
            As[nxt][ac * 4 + 0][am] = ra.x; As[nxt][ac * 4 + 1][am] = ra.y;
            As[nxt][ac * 4 + 2][am] = ra.z; As[nxt][ac * 4 + 3][am] = ra.w;
            if (BT) {
                Bs[nxt][ac * 4 + 0][am] = rb.x; Bs[nxt][ac * 4 + 1][am] = rb.y;
                Bs[nxt][ac * 4 + 2][am] = rb.z; Bs[nxt][ac * 4 + 3][am] = rb.w;
            } else {
                *(float4*)&Bs[nxt][bk][bn4] = rb;
            }
        }
        __syncthreads();
    }
}

// split-K GEMM: grid(2, N/64, S); writes partials to part[s][100][N]
template<bool BT>
__global__ __launch_bounds__(256) void gemm_split_kernel(
    const float* __restrict__ A, const float* __restrict__ B,
    float* __restrict__ part, int N, int K, int S)
{
    const int m0 = blockIdx.x * 64, n0 = blockIdx.y * 64, s = blockIdx.z;
    const int klen = K / S, kstart = s * klen, nk = klen / 16;
    const float* Ap = A + (size_t)m0 * K + kstart;
    const float* Bp = BT ? (B + (size_t)n0 * K + kstart) : (B + (size_t)kstart * N + n0);
    float acc[4][4] = {};
    gemm_mainloop<BT>(Ap, Bp, K, N, nk, 100 - m0, acc);
    float* P = part + (size_t)s * 100 * N;
    const int tx = threadIdx.x & 15, ty = threadIdx.x >> 4;
#pragma unroll
    for (int i = 0; i < 4; i++) {
        const int m = m0 + ty * 4 + i;
        if (m < 100)
            *(float4*)&P[(size_t)m * N + n0 + tx * 4] =
                make_float4(acc[i][0], acc[i][1], acc[i][2], acc[i][3]);
    }
}

// combine: out = sum_s part[s] (+bias)(relu)(+resid). Deterministic fixed order.
__global__ __launch_bounds__(256) void combine_kernel(
    const float* __restrict__ part, int S, int N,
    const float* __restrict__ bias, const float* __restrict__ resid,
    float* __restrict__ out, int relu)
{
    const int idx = (blockIdx.x * 256 + threadIdx.x) * 4;
    if (idx >= 100 * N) return;
    const int n = idx % N;
    float4 v = *(const float4*)&part[idx];
    for (int s = 1; s < S; s++) {
        const float4 p = *(const float4*)&part[(size_t)s * 100 * N + idx];
        v.x += p.x; v.y += p.y; v.z += p.z; v.w += p.w;
    }
    if (bias) {
        const float4 b = *(const float4*)&bias[n];
        v.x += b.x; v.y += b.y; v.z += b.z; v.w += b.w;
    }
    if (relu) {
        v.x = fmaxf(v.x, 0.f); v.y = fmaxf(v.y, 0.f);
        v.z = fmaxf(v.z, 0.f); v.w = fmaxf(v.w, 0.f);
    }
    if (resid) {
        const float4 r = *(const float4*)&resid[idx];
        v.x += r.x; v.y += r.y; v.z += r.z; v.w += r.w;
    }
    *(float4*)&out[idx] = v;
}

// QKV: grid(2, 4, 12). z<4: Q head z (scaled 0.1); z<8: K head z-4; else V head z-8.
__global__ __launch_bounds__(256) void qkv_kernel(
    const float* __restrict__ h, const float* __restrict__ Wq,
    const float* __restrict__ Wk, const float* __restrict__ Wv)
{
    const int z = blockIdx.z;
    const float* B;
    float* C;
    int Nc;
    float scale = 1.0f;
    if (z < 4)      { Nc = 128; B = Wq + (size_t)z * 512 * 128;       C = g_q + z * 100 * 128; scale = 0.1f; }
    else if (z < 8) { Nc = 128; B = Wk + (size_t)(z - 4) * 512 * 128; C = g_k + (z - 4) * 100 * 128; }
    else            { Nc = 256; B = Wv + (size_t)(z - 8) * 512 * 256; C = g_v + (z - 8) * 100 * 256; }
    const int n0 = blockIdx.y * 64;
    if (n0 >= Nc) return;
    const int m0 = blockIdx.x * 64;
    float acc[4][4] = {};
    gemm_mainloop<false>(h + (size_t)m0 * 512, B + n0, 512, Nc, 32, 100 - m0, acc);
    const int tx = threadIdx.x & 15, ty = threadIdx.x >> 4;
#pragma unroll
    for (int i = 0; i < 4; i++) {
        const int m = m0 + ty * 4 + i;
        if (m < 100)
            *(float4*)&C[(size_t)m * Nc + n0 + tx * 4] =
                make_float4(acc[i][0] * scale, acc[i][1] * scale,
                            acc[i][2] * scale, acc[i][3] * scale);
    }
}

// ---------------- attention: per-head K,V resident in smem ----------------
// Q pre-scaled by 0.1 (= 1/sqrt(N_LOC), faithful quirk).
#define ATTN_SMEM ((100 * 129 + 100 * 256) * 4)
__global__ __launch_bounds__(256) void attn_kernel()
{
    extern __shared__ float sm[];
    float* ks = sm;               // [100][129] padded
    float* vs = sm + 100 * 129;   // [100][256]
    __shared__ float qrow[128];
    __shared__ float srow[100];
    __shared__ float red[2];

    const int h = blockIdx.x;
    const int rg = blockIdx.y;
    const int tid = threadIdx.x;

    for (int idx = tid; idx < 100 * 128; idx += 256) {
        const int m = idx >> 7, d = idx & 127;
        ks[m * 129 + d] = g_k[h * 12800 + idx];
    }
    for (int idx = tid; idx < 100 * 256; idx += 256)
        vs[idx] = g_v[h * 25600 + idx];
    __syncthreads();

    for (int r = 0; r < 10; r++) {
        const int n = rg * 10 + r;
        if (tid < 128) qrow[tid] = g_q[(h * 100 + n) * 128 + tid];
        __syncthreads();
        if (tid < 100) {
            float acc = 0.0f;
#pragma unroll 4
            for (int d = 0; d < 128; d++) acc += qrow[d] * ks[tid * 129 + d];
            srow[tid] = acc;
        }
        __syncthreads();
        if (tid < 32) {
            float mx = -1e30f;
            for (int i = tid; i < 100; i += 32) mx = fmaxf(mx, srow[i]);
#pragma unroll
            for (int o = 16; o; o >>= 1) mx = fmaxf(mx, __shfl_xor_sync(0xffffffffu, mx, o));
            if (tid == 0) red[0] = mx;
        }
        __syncthreads();
        if (tid < 100) srow[tid] = __expf(srow[tid] - red[0]);
        __syncthreads();
        if (tid < 32) {
            float sum = 0.0f;
            for (int i = tid; i < 100; i += 32) sum += srow[i];
#pragma unroll
            for (int o = 16; o; o >>= 1) sum += __shfl_xor_sync(0xffffffffu, sum, o);
            if (tid == 0) red[1] = 1.0f / sum;
        }
        __syncthreads();
        {
            const float inv = red[1];
            const int dv = tid;  // 0..255
            float acc = 0.0f;
            for (int m = 0; m < 100; m++) acc += srow[m] * vs[m * 256 + dv];
            g_ocat[n * 1024 + h * 256 + dv] = acc * inv;
        }
        __syncthreads();
    }
}

// ---------------- launch ----------------
extern "C" void kernel_launch(void* const* d_in, const int* in_sizes, int n_in,
                              void* d_out, int out_size)
{
    (void)in_sizes; (void)n_in; (void)out_size;
    const float* x = (const float*)d_in[0];
    const float* cw[10];
    const float* cb[10];
    for (int i = 0; i < 10; i++) {
        cw[i] = (const float*)d_in[1 + 2 * i];
        cb[i] = (const float*)d_in[2 + 2 * i];
    }
    const float* Wq = (const float*)d_in[21];
    const float* Wk = (const float*)d_in[22];
    const float* Wv = (const float*)d_in[23];
    const float* Wo = (const float*)d_in[24];
    const float* W1 = (const float*)d_in[25];
    const float* b1 = (const float*)d_in[26];
    const float* W2 = (const float*)d_in[27];
    const float* b2 = (const float*)d_in[28];

    float *bufA, *bufB, *h, *ocat, *ffn, *part;
    cudaGetSymbolAddress((void**)&bufA, g_bufA);
    cudaGetSymbolAddress((void**)&bufB, g_bufB);
    cudaGetSymbolAddress((void**)&h, g_h);
    cudaGetSymbolAddress((void**)&ocat, g_ocat);
    cudaGetSymbolAddress((void**)&ffn, g_ffn);
    cudaGetSymbolAddress((void**)&part, g_part);

    cudaFuncSetAttribute(attn_kernel, cudaFuncAttributeMaxDynamicSharedMemorySize, ATTN_SMEM);

    // Conv stack (RELU_AFTER = F T F T T T T T T F); conv10 is a BT-GEMM.
    conv_kernel<3, 20, 8, 3, 8, false, true><<<dim3(100, 1), 128>>>(x, cw[0], cb[0], bufA);
    conv_kernel<8, 18, 16, 3, 8, true, false><<<dim3(100, 2), 128>>>(bufA, cw[1], cb[1], bufB);
    conv_kernel<16, 16, 32, 3, 8, false, false><<<dim3(100, 4), 128>>>(bufB, cw[2], cb[2], bufA);
    conv_kernel<32, 14, 32, 3, 8, true, false><<<dim3(100, 4), 128>>>(bufA, cw[3], cb[3], bufB);
    conv_kernel<32, 12, 64, 3, 16, true, false><<<dim3(100, 4), 128>>>(bufB, cw[4], cb[4], bufA);
    conv_kernel<64, 10, 64, 3, 16, true, false><<<dim3(100, 4), 128>>>(bufA, cw[5], cb[5], bufB);
    conv_kernel<64, 8, 128, 3, 32, true, false><<<dim3(100, 4), 128>>>(bufB, cw[6], cb[6], bufA);
    conv_kernel<128, 6, 128, 3, 32, true, false><<<dim3(100, 4), 128>>>(bufA, cw[7], cb[7], bufB);
    conv_kernel<128, 4, 256, 3, 64, true, false><<<dim3(100, 4), 128>>>(bufB, cw[8], cb[8], bufA);
    // conv10: [100,1024] @ W10^T[1024,512] + b10  (S=4 split-K)
    gemm_split_kernel<true><<<dim3(2, 8, 4), 256>>>(bufA, cw[9], part, 512, 1024, 4);
    combine_kernel<<<50, 256>>>(part, 4, 512, cb[9], nullptr, bufB, 0);

    locadd_kernel<<<200, 256>>>(bufB, h);

    for (int n = 0; n < 12; n++) {
        qkv_kernel<<<dim3(2, 4, 12), 256>>>(h, Wq + (size_t)n * 262144,
                                            Wk + (size_t)n * 262144,
                                            Wv + (size_t)n * 524288);
        attn_kernel<<<dim3(4, 10), 256, ATTN_SMEM>>>();
        // h = h + ocat @ Wo   (S=4)
        gemm_split_kernel<false><<<dim3(2, 8, 4), 256>>>(ocat, Wo + (size_t)n * 524288,
                                                         part, 512, 1024, 4);
        combine_kernel<<<50, 256>>>(part, 4, 512, nullptr, h, h, 0);
        // ffn = relu(h @ W1 + b1)   (S=2)
        gemm_split_kernel<false><<<dim3(2, 32, 2), 256>>>(h, W1 + (size_t)n * 1048576,
                                                          part, 2048, 512, 2);
        combine_kernel<<<200, 256>>>(part, 2, 2048, b1 + (size_t)n * 2048, nullptr, ffn, 1);
        // h = h + ffn @ W2 + b2   (S=8; last layer -> d_out)
        float* outp = (n == 11) ? (float*)d_out : h;
        gemm_split_kernel<false><<<dim3(2, 8, 8), 256>>>(ffn, W2 + (size_t)n * 1048576,
                                                         part, 512, 2048, 8);
        combine_kernel<<<50, 256>>>(part, 8, 512, b2 + (size_t)n * 512, h, outp, 0);
    }
}

// round 6
// speedup vs baseline: 3.3480x; 1.1760x over previous
#include <cuda_runtime.h>
#include <cuda_bf16.h>
#include <mma.h>
#include <math.h>
#include <stdint.h>

using namespace nvcuda;

// ---------------- scratch (allocation-free: __device__ globals) ----------------
__device__ float g_bufA[660000];
__device__ float g_bufB[660000];
__device__ float g_h[100 * 512];
__device__ float g_q[4 * 100 * 128];
__device__ float g_k[4 * 100 * 128];
__device__ float g_v[4 * 100 * 256];
__device__ float g_ocat[100 * 1024];
__device__ float g_ffn[100 * 2048];
__device__ float g_part[409600];   // split-K partials

// ================= HMMA (mma.sync bf16, 3-term split) GEMM ====================
// CTA: 128 threads (4 warps), tile M=64 x N=64, K chunks of 64.
// Split-bf16: a = ah + al (hi/lo bf16), C += Ah*Bh + Ah*Bl + Al*Bh in fp32.
struct __align__(32) HSM {
    __nv_bfloat16 Ah[64 * 80];
    __nv_bfloat16 Al[64 * 80];
    __nv_bfloat16 Bh[64 * 80];
    __nv_bfloat16 Bl[64 * 80];
};
union __align__(32) HU {
    HSM s;
    float C[64 * 64];
};

__device__ __forceinline__ uint32_t bf2pack(__nv_bfloat16 a, __nv_bfloat16 b) {
    __nv_bfloat162 t(a, b);
    return *reinterpret_cast<uint32_t*>(&t);
}

// A: pre-offset to tile row base, row stride K. mvalid = valid rows in tile.
// B (NKW=false): [K,N] rows, pre-offset kstart*ldB + n0, ldB = N.
// B (NKW=true):  [N,K] rows, pre-offset n0*ldB + kstart, ldB = K.
template <bool NKW>
__device__ __forceinline__ void hmma_core(
    HU& u, const float* __restrict__ A, int K,
    const float* __restrict__ B, int ldB, int nk, int mvalid)
{
    const int t = threadIdx.x;
    const int wid = t >> 5;
    const int wm = wid >> 1, wn = wid & 1;

    wmma::fragment<wmma::accumulator, 16, 16, 16, float> c[2][2];
#pragma unroll
    for (int i = 0; i < 2; i++)
#pragma unroll
        for (int j = 0; j < 2; j++) wmma::fill_fragment(c[i][j], 0.0f);

    for (int kt = 0; kt < nk; kt++) {
        const int k0 = kt << 6;
        // ---- stage A (64x64 fp32 -> hi/lo bf16) ----
#pragma unroll
        for (int i = 0; i < 8; i++) {
            const int e = t + (i << 7);
            const int m = e >> 4, k4 = (e & 15) << 2;
            float4 v = make_float4(0.f, 0.f, 0.f, 0.f);
            if (m < mvalid) v = *(const float4*)(A + (size_t)m * K + k0 + k4);
            const __nv_bfloat16 h0 = __float2bfloat16_rn(v.x), h1 = __float2bfloat16_rn(v.y),
                                h2 = __float2bfloat16_rn(v.z), h3 = __float2bfloat16_rn(v.w);
            const __nv_bfloat16 l0 = __float2bfloat16_rn(v.x - __bfloat162float(h0)),
                                l1 = __float2bfloat16_rn(v.y - __bfloat162float(h1)),
                                l2 = __float2bfloat16_rn(v.z - __bfloat162float(h2)),
                                l3 = __float2bfloat16_rn(v.w - __bfloat162float(h3));
            uint2 uh, ul;
            uh.x = bf2pack(h0, h1); uh.y = bf2pack(h2, h3);
            ul.x = bf2pack(l0, l1); ul.y = bf2pack(l2, l3);
            *(uint2*)&u.s.Ah[m * 80 + k4] = uh;
            *(uint2*)&u.s.Al[m * 80 + k4] = ul;
        }
        // ---- stage B (-> [k][n] hi/lo bf16) ----
#pragma unroll
        for (int i = 0; i < 8; i++) {
            const int e = t + (i << 7);
            if (!NKW) {
                const int k = e >> 4, n4 = (e & 15) << 2;
                const float4 v = *(const float4*)(B + (size_t)(k0 + k) * ldB + n4);
                const __nv_bfloat16 h0 = __float2bfloat16_rn(v.x), h1 = __float2bfloat16_rn(v.y),
                                    h2 = __float2bfloat16_rn(v.z), h3 = __float2bfloat16_rn(v.w);
                uint2 uh, ul;
                uh.x = bf2pack(h0, h1); uh.y = bf2pack(h2, h3);
                ul.x = bf2pack(__float2bfloat16_rn(v.x - __bfloat162float(h0)),
                               __float2bfloat16_rn(v.y - __bfloat162float(h1)));
                ul.y = bf2pack(__float2bfloat16_rn(v.z - __bfloat162float(h2)),
                               __float2bfloat16_rn(v.w - __bfloat162float(h3)));
                *(uint2*)&u.s.Bh[k * 80 + n4] = uh;
                *(uint2*)&u.s.Bl[k * 80 + n4] = ul;
            } else {
                const int n = e >> 4, k4 = (e & 15) << 2;
                const float4 v = *(const float4*)(B + (size_t)n * ldB + k0 + k4);
                const float vv[4] = {v.x, v.y, v.z, v.w};
#pragma unroll
                for (int j = 0; j < 4; j++) {
                    const __nv_bfloat16 hb = __float2bfloat16_rn(vv[j]);
                    u.s.Bh[(k4 + j) * 80 + n] = hb;
                    u.s.Bl[(k4 + j) * 80 + n] =
                        __float2bfloat16_rn(vv[j] - __bfloat162float(hb));
                }
            }
        }
        __syncthreads();
        // ---- compute: 4 k16-steps, 3-term ----
#pragma unroll
        for (int kk = 0; kk < 4; kk++) {
            wmma::fragment<wmma::matrix_a, 16, 16, 16, __nv_bfloat16, wmma::row_major> ah[2], al[2];
            wmma::fragment<wmma::matrix_b, 16, 16, 16, __nv_bfloat16, wmma::row_major> bh[2], bl[2];
#pragma unroll
            for (int i = 0; i < 2; i++) {
                wmma::load_matrix_sync(ah[i], &u.s.Ah[(wm * 32 + i * 16) * 80 + kk * 16], 80);
                wmma::load_matrix_sync(al[i], &u.s.Al[(wm * 32 + i * 16) * 80 + kk * 16], 80);
            }
#pragma unroll
            for (int j = 0; j < 2; j++) {
                wmma::load_matrix_sync(bh[j], &u.s.Bh[(kk * 16) * 80 + wn * 32 + j * 16], 80);
                wmma::load_matrix_sync(bl[j], &u.s.Bl[(kk * 16) * 80 + wn * 32 + j * 16], 80);
            }
#pragma unroll
            for (int i = 0; i < 2; i++)
#pragma unroll
                for (int j = 0; j < 2; j++) {
                    wmma::mma_sync(c[i][j], ah[i], bh[j], c[i][j]);
                    wmma::mma_sync(c[i][j], ah[i], bl[j], c[i][j]);
                    wmma::mma_sync(c[i][j], al[i], bh[j], c[i][j]);
                }
        }
        __syncthreads();
    }
    // ---- store accumulators to smem C ----
#pragma unroll
    for (int i = 0; i < 2; i++)
#pragma unroll
        for (int j = 0; j < 2; j++)
            wmma::store_matrix_sync(&u.C[(wm * 32 + i * 16) * 64 + wn * 32 + j * 16],
                                    c[i][j], 64, wmma::mem_row_major);
    __syncthreads();
}

// split-K GEMM: grid(2, N/64, S); partials to part[s][100][N]
template <bool NKW>
__global__ __launch_bounds__(128) void hmma_split_kernel(
    const float* __restrict__ A, const float* __restrict__ B,
    float* __restrict__ part, int N, int K, int S)
{
    __shared__ HU u;
    const int m0 = blockIdx.x * 64, n0 = blockIdx.y * 64, s = blockIdx.z;
    const int klen = K / S, kstart = s * klen;
    const float* Ap = A + (size_t)m0 * K + kstart;
    const float* Bp = NKW ? (B + (size_t)n0 * K + kstart) : (B + (size_t)kstart * N + n0);
    hmma_core<NKW>(u, Ap, K, Bp, NKW ? K : N, klen >> 6, 100 - m0);
    float* P = part + ((size_t)s * 100 + m0) * N + n0;
    const int t = threadIdx.x;
#pragma unroll
    for (int i = 0; i < 8; i++) {
        const int e = t + (i << 7);
        const int m = e >> 4, n4 = (e & 15) << 2;
        if (m0 + m < 100)
            *(float4*)&P[(size_t)m * N + n4] = *(float4*)&u.C[m * 64 + n4];
    }
}

// combine: out = sum_s part[s] (+bias)(relu)(+resid). Deterministic fixed order.
__global__ __launch_bounds__(256) void combine_kernel(
    const float* __restrict__ part, int S, int N,
    const float* __restrict__ bias, const float* __restrict__ resid,
    float* __restrict__ out, int relu)
{
    const int idx = (blockIdx.x * 256 + threadIdx.x) * 4;
    if (idx >= 100 * N) return;
    const int n = idx % N;
    float4 v = *(const float4*)&part[idx];
    for (int s = 1; s < S; s++) {
        const float4 p = *(const float4*)&part[(size_t)s * 100 * N + idx];
        v.x += p.x; v.y += p.y; v.z += p.z; v.w += p.w;
    }
    if (bias) {
        const float4 b = *(const float4*)&bias[n];
        v.x += b.x; v.y += b.y; v.z += b.z; v.w += b.w;
    }
    if (relu) {
        v.x = fmaxf(v.x, 0.f); v.y = fmaxf(v.y, 0.f);
        v.z = fmaxf(v.z, 0.f); v.w = fmaxf(v.w, 0.f);
    }
    if (resid) {
        const float4 r = *(const float4*)&resid[idx];
        v.x += r.x; v.y += r.y; v.z += r.z; v.w += r.w;
    }
    *(float4*)&out[idx] = v;
}

// QKV: grid(2, 4, 12). z<4: Q head z (scale 0.1); z<8: K; else V. K=512, no split.
__global__ __launch_bounds__(128) void hmma_qkv_kernel(
    const float* __restrict__ h, const float* __restrict__ Wq,
    const float* __restrict__ Wk, const float* __restrict__ Wv)
{
    const int z = blockIdx.z;
    const float* B;
    float* C;
    int Nc;
    float scale = 1.0f;
    if (z < 4)      { Nc = 128; B = Wq + (size_t)z * 65536;        C = g_q + z * 12800; scale = 0.1f; }
    else if (z < 8) { Nc = 128; B = Wk + (size_t)(z - 4) * 65536;  C = g_k + (z - 4) * 12800; }
    else            { Nc = 256; B = Wv + (size_t)(z - 8) * 131072; C = g_v + (z - 8) * 25600; }
    const int n0 = blockIdx.y * 64;
    if (n0 >= Nc) return;
    const int m0 = blockIdx.x * 64;
    __shared__ HU u;
    hmma_core<false>(u, h + (size_t)m0 * 512, 512, B + n0, Nc, 8, 100 - m0);
    float* Cp = C + (size_t)m0 * Nc + n0;
    const int t = threadIdx.x;
#pragma unroll
    for (int i = 0; i < 8; i++) {
        const int e = t + (i << 7);
        const int m = e >> 4, n4 = (e & 15) << 2;
        if (m0 + m < 100) {
            float4 v = *(float4*)&u.C[m * 64 + n4];
            v.x *= scale; v.y *= scale; v.z *= scale; v.w *= scale;
            *(float4*)&Cp[(size_t)m * Nc + n4] = v;
        }
    }
}

// ---------------- conv layers 1-9 (row-strip kernel) ----------------
template <int CIN, int HIN, int COUT, int KS, int COG, bool RELU, bool FIRST>
__global__ __launch_bounds__(128) void conv_kernel(
    const float* __restrict__ in, const float* __restrict__ W,
    const float* __restrict__ bias, float* __restrict__ out)
{
    constexpr int HOUT = HIN - KS + 1;
    constexpr int WOUT = HOUT;
    constexpr int INSZ = CIN * HIN * HIN;
    constexpr int HW = HOUT * WOUT;
    __shared__ float sin_[INSZ];

    const int p = blockIdx.x;
    const int co0 = blockIdx.y * COG;

    if (FIRST) {
        const int ib = p / 10, jb = p % 10;
        for (int idx = threadIdx.x; idx < INSZ; idx += blockDim.x) {
            const int c = idx / (HIN * HIN);
            const int rem = idx % (HIN * HIN);
            const int r = rem / HIN, cc = rem % HIN;
            sin_[idx] = in[c * 40000 + (20 * jb + r) * 200 + (20 * ib + cc)];
        }
    } else {
        const float* src = in + p * INSZ;
        for (int idx = threadIdx.x; idx < INSZ; idx += blockDim.x)
            sin_[idx] = src[idx];
    }
    __syncthreads();

    for (int pair = threadIdx.x; pair < COG * HOUT; pair += blockDim.x) {
        const int co = co0 + pair / HOUT;
        const int py = pair % HOUT;
        float acc[WOUT];
        const float bv = bias[co];
#pragma unroll
        for (int px = 0; px < WOUT; px++) acc[px] = bv;
        const float* wbase = W + co * CIN * KS * KS;
        for (int ci = 0; ci < CIN; ci++) {
#pragma unroll
            for (int ky = 0; ky < KS; ky++) {
                const float* irow = sin_ + ci * HIN * HIN + (py + ky) * HIN;
                float w[KS];
#pragma unroll
                for (int kx = 0; kx < KS; kx++)
                    w[kx] = wbase[ci * KS * KS + ky * KS + kx];
#pragma unroll
                for (int px = 0; px < WOUT; px++) {
#pragma unroll
                    for (int kx = 0; kx < KS; kx++)
                        acc[px] += w[kx] * irow[px + kx];
                }
            }
        }
        float* orow = out + p * COUT * HW + co * HW + py * WOUT;
#pragma unroll
        for (int px = 0; px < WOUT; px++) {
            float v = acc[px];
            if (RELU) v = fmaxf(v, 0.0f);
            orow[px] = v;
        }
    }
}

// ---------------- location embedding add ----------------
__global__ __launch_bounds__(256) void locadd_kernel(const float* __restrict__ conv_out,
                                                     float* __restrict__ h)
{
    int i = blockIdx.x * blockDim.x + threadIdx.x;
    if (i >= 100 * 512) return;
    const int n = i >> 9;
    const int d = i & 511;
    const float pos = 20.0f * (float)(n / 10);
    const int k = d & 255;
    const float ang = pos * exp2f(-0.10381025296523009f * (float)k);
    const float e = (d < 256) ? sinf(ang) : cosf(ang);
    h[i] = conv_out[i] + e;
}

// ---------------- attention (fp32; Q pre-scaled by 0.1) ----------------
#define ATTN_SMEM ((100 * 129 + 100 * 256) * 4)
__global__ __launch_bounds__(256) void attn_kernel()
{
    extern __shared__ float sm[];
    float* ks = sm;
    float* vs = sm + 100 * 129;
    __shared__ float qrow[128];
    __shared__ float srow[100];
    __shared__ float red[2];

    const int h = blockIdx.x;
    const int rg = blockIdx.y;
    const int tid = threadIdx.x;

    for (int idx = tid; idx < 100 * 128; idx += 256) {
        const int m = idx >> 7, d = idx & 127;
        ks[m * 129 + d] = g_k[h * 12800 + idx];
    }
    for (int idx = tid; idx < 100 * 256; idx += 256)
        vs[idx] = g_v[h * 25600 + idx];
    __syncthreads();

    for (int r = 0; r < 10; r++) {
        const int n = rg * 10 + r;
        if (tid < 128) qrow[tid] = g_q[(h * 100 + n) * 128 + tid];
        __syncthreads();
        if (tid < 100) {
            float acc = 0.0f;
#pragma unroll 4
            for (int d = 0; d < 128; d++) acc += qrow[d] * ks[tid * 129 + d];
            srow[tid] = acc;
        }
        __syncthreads();
        if (tid < 32) {
            float mx = -1e30f;
            for (int i = tid; i < 100; i += 32) mx = fmaxf(mx, srow[i]);
#pragma unroll
            for (int o = 16; o; o >>= 1) mx = fmaxf(mx, __shfl_xor_sync(0xffffffffu, mx, o));
            if (tid == 0) red[0] = mx;
        }
        __syncthreads();
        if (tid < 100) srow[tid] = __expf(srow[tid] - red[0]);
        __syncthreads();
        if (tid < 32) {
            float sum = 0.0f;
            for (int i = tid; i < 100; i += 32) sum += srow[i];
#pragma unroll
            for (int o = 16; o; o >>= 1) sum += __shfl_xor_sync(0xffffffffu, sum, o);
            if (tid == 0) red[1] = 1.0f / sum;
        }
        __syncthreads();
        {
            const float inv = red[1];
            const int dv = tid;
            float acc = 0.0f;
            for (int m = 0; m < 100; m++) acc += srow[m] * vs[m * 256 + dv];
            g_ocat[n * 1024 + h * 256 + dv] = acc * inv;
        }
        __syncthreads();
    }
}

// ---------------- launch ----------------
extern "C" void kernel_launch(void* const* d_in, const int* in_sizes, int n_in,
                              void* d_out, int out_size)
{
    (void)in_sizes; (void)n_in; (void)out_size;
    const float* x = (const float*)d_in[0];
    const float* cw[10];
    const float* cb[10];
    for (int i = 0; i < 10; i++) {
        cw[i] = (const float*)d_in[1 + 2 * i];
        cb[i] = (const float*)d_in[2 + 2 * i];
    }
    const float* Wq = (const float*)d_in[21];
    const float* Wk = (const float*)d_in[22];
    const float* Wv = (const float*)d_in[23];
    const float* Wo = (const float*)d_in[24];
    const float* W1 = (const float*)d_in[25];
    const float* b1 = (const float*)d_in[26];
    const float* W2 = (const float*)d_in[27];
    const float* b2 = (const float*)d_in[28];

    float *bufA, *bufB, *h, *ocat, *ffn, *part;
    cudaGetSymbolAddress((void**)&bufA, g_bufA);
    cudaGetSymbolAddress((void**)&bufB, g_bufB);
    cudaGetSymbolAddress((void**)&h, g_h);
    cudaGetSymbolAddress((void**)&ocat, g_ocat);
    cudaGetSymbolAddress((void**)&ffn, g_ffn);
    cudaGetSymbolAddress((void**)&part, g_part);

    cudaFuncSetAttribute(attn_kernel, cudaFuncAttributeMaxDynamicSharedMemorySize, ATTN_SMEM);

    // Conv stack (RELU_AFTER = F T F T T T T T T F); conv10 = HMMA BT-GEMM.
    conv_kernel<3, 20, 8, 3, 8, false, true><<<dim3(100, 1), 128>>>(x, cw[0], cb[0], bufA);
    conv_kernel<8, 18, 16, 3, 8, true, false><<<dim3(100, 2), 128>>>(bufA, cw[1], cb[1], bufB);
    conv_kernel<16, 16, 32, 3, 8, false, false><<<dim3(100, 4), 128>>>(bufB, cw[2], cb[2], bufA);
    conv_kernel<32, 14, 32, 3, 8, true, false><<<dim3(100, 4), 128>>>(bufA, cw[3], cb[3], bufB);
    conv_kernel<32, 12, 64, 3, 16, true, false><<<dim3(100, 4), 128>>>(bufB, cw[4], cb[4], bufA);
    conv_kernel<64, 10, 64, 3, 16, true, false><<<dim3(100, 4), 128>>>(bufA, cw[5], cb[5], bufB);
    conv_kernel<64, 8, 128, 3, 32, true, false><<<dim3(100, 4), 128>>>(bufB, cw[6], cb[6], bufA);
    conv_kernel<128, 6, 128, 3, 32, true, false><<<dim3(100, 4), 128>>>(bufA, cw[7], cb[7], bufB);
    conv_kernel<128, 4, 256, 3, 64, true, false><<<dim3(100, 4), 128>>>(bufB, cw[8], cb[8], bufA);
    // conv10: [100,1024] @ W10^T + b10  (S=4)
    hmma_split_kernel<true><<<dim3(2, 8, 4), 128>>>(bufA, cw[9], part, 512, 1024, 4);
    combine_kernel<<<50, 256>>>(part, 4, 512, cb[9], nullptr, bufB, 0);

    locadd_kernel<<<200, 256>>>(bufB, h);

    for (int n = 0; n < 12; n++) {
        hmma_qkv_kernel<<<dim3(2, 4, 12), 128>>>(h, Wq + (size_t)n * 262144,
                                                 Wk + (size_t)n * 262144,
                                                 Wv + (size_t)n * 524288);
        attn_kernel<<<dim3(4, 10), 256, ATTN_SMEM>>>();
        // h = h + ocat @ Wo   (S=4)
        hmma_split_kernel<false><<<dim3(2, 8, 4), 128>>>(ocat, Wo + (size_t)n * 524288,
                                                         part, 512, 1024, 4);
        combine_kernel<<<50, 256>>>(part, 4, 512, nullptr, h, h, 0);
        // ffn = relu(h @ W1 + b1)   (S=2)
        hmma_split_kernel<false><<<dim3(2, 32, 2), 128>>>(h, W1 + (size_t)n * 1048576,
                                                          part, 2048, 512, 2);
        combine_kernel<<<200, 256>>>(part, 2, 2048, b1 + (size_t)n * 2048, nullptr, ffn, 1);
        // h = h + ffn @ W2 + b2   (S=8; last layer -> d_out)
        float* outp = (n == 11) ? (float*)d_out : h;
        hmma_split_kernel<false><<<dim3(2, 8, 8), 128>>>(ffn, W2 + (size_t)n * 1048576,
                                                         part, 512, 2048, 8);
        combine_kernel<<<50, 256>>>(part, 8, 512, b2 + (size_t)n * 512, h, outp, 0);
    }
}